// round 16
// baseline (speedup 1.0000x reference)
#include <cuda_runtime.h>
#include <cuda_fp16.h>
#include <cstdint>

#define GN      8192
#define NELEM   ((size_t)GN * GN)
#define KSTAGE  32
#define NITERS  (GN / KSTAGE)          // 256
#define TPB     128

#define A_STRIDE    80                 // bytes per A smem row (32 halves + 8 pad)
#define B_STRIDE    272                // bytes per B smem row (128 halves + 8 pad)
#define A_TILE      (128 * A_STRIDE)   // 10240
#define B_TILE      (32 * B_STRIDE)    // 8704
#define STAGES      4
#define STAGE       (A_TILE + B_TILE)  // 18944
#define SMEM_DYN    (STAGES * STAGE + 1024)   // 76800 -> 3 CTAs/SM (reg-capped anyway)

// fp16 scratch copies of the f32 inputs (128 MB each; static device memory)
__device__ __half g_A[NELEM];
__device__ __half g_B[NELEM];

__device__ __forceinline__ uint32_t smem_u32(const void* p) {
    uint32_t a;
    asm("{ .reg .u64 t; cvta.to.shared.u64 t, %1; cvt.u32.u64 %0, t; }" : "=r"(a) : "l"(p));
    return a;
}
__device__ __forceinline__ void cpasync16(uint32_t dst, const void* src) {
    asm volatile("cp.async.cg.shared.global [%0], [%1], 16;" :: "r"(dst), "l"(src) : "memory");
}
#define CP_COMMIT() asm volatile("cp.async.commit_group;" ::: "memory")
#define CP_WAIT2()  asm volatile("cp.async.wait_group 2;" ::: "memory")

#define LDSM_X4(r, a) \
    asm volatile("ldmatrix.sync.aligned.m8n8.x4.shared.b16 {%0,%1,%2,%3}, [%4];" \
        : "=r"((r)[0]), "=r"((r)[1]), "=r"((r)[2]), "=r"((r)[3]) : "r"(a))
#define LDSM_X4T(r, a) \
    asm volatile("ldmatrix.sync.aligned.m8n8.x4.trans.shared.b16 {%0,%1,%2,%3}, [%4];" \
        : "=r"((r)[0]), "=r"((r)[1]), "=r"((r)[2]), "=r"((r)[3]) : "r"(a))

__device__ __forceinline__ void mma16816(float* d, const uint32_t* a, const uint32_t* b) {
    asm volatile("mma.sync.aligned.m16n8k16.row.col.f32.f16.f16.f32 "
        "{%0,%1,%2,%3}, {%4,%5,%6,%7}, {%8,%9}, {%0,%1,%2,%3};"
        : "+f"(d[0]), "+f"(d[1]), "+f"(d[2]), "+f"(d[3])
        : "r"(a[0]), "r"(a[1]), "r"(a[2]), "r"(a[3]), "r"(b[0]), "r"(b[1]));
}

__device__ __forceinline__ float h2f_round(float v) {
    return __half2float(__float2half_rn(v));
}

// ---- prepass: f32 (fp16-valued) -> packed fp16; 8 elems/thread, 16B stores ----
__global__ void cvt_k(const float4* __restrict__ a, const float4* __restrict__ b)
{
    size_t n8 = NELEM / 8;
    size_t stride = (size_t)gridDim.x * blockDim.x;
    for (size_t i = (size_t)blockIdx.x * blockDim.x + threadIdx.x; i < n8; i += stride) {
        float4 va0 = a[2 * i], va1 = a[2 * i + 1];
        __half2 h0 = __floats2half2_rn(va0.x, va0.y);
        __half2 h1 = __floats2half2_rn(va0.z, va0.w);
        __half2 h2 = __floats2half2_rn(va1.x, va1.y);
        __half2 h3 = __floats2half2_rn(va1.z, va1.w);
        uint4 ua = make_uint4(*reinterpret_cast<uint32_t*>(&h0),
                              *reinterpret_cast<uint32_t*>(&h1),
                              *reinterpret_cast<uint32_t*>(&h2),
                              *reinterpret_cast<uint32_t*>(&h3));
        *reinterpret_cast<uint4*>(&g_A[8 * i]) = ua;

        float4 vb0 = b[2 * i], vb1 = b[2 * i + 1];
        h0 = __floats2half2_rn(vb0.x, vb0.y);
        h1 = __floats2half2_rn(vb0.z, vb0.w);
        h2 = __floats2half2_rn(vb1.x, vb1.y);
        h3 = __floats2half2_rn(vb1.z, vb1.w);
        uint4 ub = make_uint4(*reinterpret_cast<uint32_t*>(&h0),
                              *reinterpret_cast<uint32_t*>(&h1),
                              *reinterpret_cast<uint32_t*>(&h2),
                              *reinterpret_cast<uint32_t*>(&h3));
        *reinterpret_cast<uint4*>(&g_B[8 * i]) = ub;
    }
}

// ---- main: 128x128 tile, 4 warps (2m x 2n) of 64x64, 3 CTAs/SM ----
__global__ void __launch_bounds__(TPB, 3)
triu_mm_k(float* __restrict__ C)
{
    int bid = blockIdx.x;
    int tid = threadIdx.x, wid = tid >> 5, lane = tid & 31;

    // 16-row supertile rasterization over the 64x64 tile grid (L2 reuse)
    int mt = ((bid >> 10) << 4) | (bid & 15);
    int nt = (bid & 1023) >> 4;
    int m0 = mt * 128, n0 = nt * 128;

    if (nt < mt) {                              // strictly-lower: zero-fill f32
        float* base = C + (size_t)m0 * GN + n0;
        uint4 z = make_uint4(0, 0, 0, 0);
        for (int i = tid; i < 128 * 32; i += TPB)
            *reinterpret_cast<uint4*>(base + (size_t)(i >> 5) * GN + ((i & 31) << 2)) = z;
        return;
    }

    extern __shared__ char smraw[];
    uint32_t sb = (smem_u32(smraw) + 1023u) & ~1023u;
    int warp_m = (wid & 1) * 64;                // 2m x 2n warps: 64x64 per warp
    int warp_n = (wid >> 1) * 64;

    float acc[4][8][4];
    #pragma unroll
    for (int i = 0; i < 4; i++)
        #pragma unroll
        for (int j = 0; j < 8; j++)
            #pragma unroll
            for (int k = 0; k < 4; k++) acc[i][j][k] = 0.0f;

    // hoisted LDSM offsets (relative to stage base)
    uint32_t a_off[4], b_off[4];
    #pragma unroll
    for (int mb = 0; mb < 4; mb++)
        a_off[mb] = (uint32_t)(warp_m + mb * 16 + (lane & 15)) * A_STRIDE
                    + ((lane >> 4) << 4);
    #pragma unroll
    for (int nb = 0; nb < 4; nb++)
        b_off[nb] = (uint32_t)(lane & 15) * B_STRIDE + A_TILE
                    + (uint32_t)(warp_n + nb * 16) * 2 + ((lane >> 4) << 4);

    auto load_stage = [&](int slot, int ks) {
        uint32_t abase = sb + slot * STAGE;
        uint32_t bbase = abase + A_TILE;
        int k0 = ks * KSTAGE;
        #pragma unroll
        for (int j = 0; j < 4; j++) {           // A: 128 rows x 4 x 16B
            int c = tid + j * TPB;
            int r = c >> 2, kc = c & 3;
            cpasync16(abase + r * A_STRIDE + kc * 16,
                      g_A + (size_t)(m0 + r) * GN + k0 + kc * 8);
        }
        #pragma unroll
        for (int j = 0; j < 4; j++) {           // B: 32 k-rows x 16 x 16B
            int c = tid + j * TPB;
            int kr = c >> 4, nc = c & 15;
            cpasync16(bbase + kr * B_STRIDE + nc * 16,
                      g_B + (size_t)(k0 + kr) * GN + n0 + nc * 8);
        }
        CP_COMMIT();
    };

    for (int s = 0; s < STAGES - 1; s++) load_stage(s, s);   // prefetch 0..2

    for (int i = 0; i < NITERS; i++) {
        CP_WAIT2();                 // stage i resident (<=2 newer groups pending)
        __syncthreads();            // all warps past iter i-1 -> slot (i+3)%4 free
        if (i + STAGES - 1 < NITERS)
            load_stage((i + STAGES - 1) % STAGES, i + STAGES - 1);
        else
            CP_COMMIT();            // keep wait_group invariant through the drain

        uint32_t abase = sb + (i % STAGES) * STAGE;
        #pragma unroll
        for (int kk = 0; kk < 2; kk++) {        // 2 x k16 per stage
            uint32_t af[4][4];
            uint32_t a_kk = abase + (kk << 5);  // +32B along K
            #pragma unroll
            for (int mb = 0; mb < 4; mb++)
                LDSM_X4(af[mb], a_kk + a_off[mb]);
            uint32_t b_kk = abase + kk * (16 * B_STRIDE);
            #pragma unroll
            for (int half = 0; half < 2; half++) {
                uint32_t bf[2][4];
                #pragma unroll
                for (int nb = 0; nb < 2; nb++)
                    LDSM_X4T(bf[nb], b_kk + b_off[half * 2 + nb]);
                #pragma unroll
                for (int mb = 0; mb < 4; mb++)
                    #pragma unroll
                    for (int nj = 0; nj < 4; nj++)
                        mma16816(acc[mb][half * 4 + nj], af[mb],
                                 &bf[nj >> 1][(nj & 1) * 2]);
            }
        }
    }

    // ---- epilogue: triu mask + fp16-rounded float32 stores ----
    #pragma unroll
    for (int mb = 0; mb < 4; mb++) {
        #pragma unroll
        for (int nj = 0; nj < 8; nj++) {
            int gr = m0 + warp_m + mb * 16 + (lane >> 2);
            int gc = n0 + warp_n + nj * 8 + ((lane & 3) << 1);
            float* d = acc[mb][nj];
            {
                float2 v;
                v.x = (gc >= gr)     ? h2f_round(d[0]) : 0.0f;
                v.y = (gc + 1 >= gr) ? h2f_round(d[1]) : 0.0f;
                *reinterpret_cast<float2*>(C + (size_t)gr * GN + gc) = v;
            }
            {
                int gr2 = gr + 8;
                float2 v;
                v.x = (gc >= gr2)     ? h2f_round(d[2]) : 0.0f;
                v.y = (gc + 1 >= gr2) ? h2f_round(d[3]) : 0.0f;
                *reinterpret_cast<float2*>(C + (size_t)gr2 * GN + gc) = v;
            }
        }
    }
}

extern "C" void kernel_launch(void* const* d_in, const int* in_sizes, int n_in,
                              void* d_out, int out_size)
{
    (void)in_sizes; (void)n_in; (void)out_size;
    cvt_k<<<16384, 256>>>((const float4*)d_in[0], (const float4*)d_in[1]);
    cudaFuncSetAttribute(triu_mm_k, cudaFuncAttributeMaxDynamicSharedMemorySize, SMEM_DYN);
    triu_mm_k<<<64 * 64, TPB, SMEM_DYN>>>((float*)d_out);
}

// round 17
// speedup vs baseline: 1.0468x; 1.0468x over previous
#include <cuda_runtime.h>
#include <cuda_fp16.h>
#include <cstdint>

#define GN      8192
#define NELEM   ((size_t)GN * GN)
#define KSTAGE  64
#define NITERS  (GN / KSTAGE)          // 128
#define TPB     128

#define A_STRIDE    144                // bytes per A smem row (64 halves + 8 pad)
#define B_STRIDE    272                // bytes per B smem row (128 halves + 8 pad)
#define A_TILE      (128 * A_STRIDE)   // 18432
#define B_TILE      (64 * B_STRIDE)    // 17408
#define STAGES      2
#define STAGE       (A_TILE + B_TILE)  // 35840
#define SMEM_DYN    (STAGES * STAGE + 1024)   // 72704 -> 3 CTAs/SM

// fp16 scratch copies of the f32 inputs (128 MB each; static device memory)
__device__ __half g_A[NELEM];
__device__ __half g_B[NELEM];

__device__ __forceinline__ uint32_t smem_u32(const void* p) {
    uint32_t a;
    asm("{ .reg .u64 t; cvta.to.shared.u64 t, %1; cvt.u32.u64 %0, t; }" : "=r"(a) : "l"(p));
    return a;
}
__device__ __forceinline__ void cpasync16(uint32_t dst, const void* src) {
    asm volatile("cp.async.cg.shared.global [%0], [%1], 16;" :: "r"(dst), "l"(src) : "memory");
}
#define CP_COMMIT() asm volatile("cp.async.commit_group;" ::: "memory")
#define CP_WAIT0()  asm volatile("cp.async.wait_group 0;" ::: "memory")

#define LDSM_X4(r, a) \
    asm volatile("ldmatrix.sync.aligned.m8n8.x4.shared.b16 {%0,%1,%2,%3}, [%4];" \
        : "=r"((r)[0]), "=r"((r)[1]), "=r"((r)[2]), "=r"((r)[3]) : "r"(a))
#define LDSM_X4T(r, a) \
    asm volatile("ldmatrix.sync.aligned.m8n8.x4.trans.shared.b16 {%0,%1,%2,%3}, [%4];" \
        : "=r"((r)[0]), "=r"((r)[1]), "=r"((r)[2]), "=r"((r)[3]) : "r"(a))

__device__ __forceinline__ void mma16816(float* d, const uint32_t* a, const uint32_t* b) {
    asm volatile("mma.sync.aligned.m16n8k16.row.col.f32.f16.f16.f32 "
        "{%0,%1,%2,%3}, {%4,%5,%6,%7}, {%8,%9}, {%0,%1,%2,%3};"
        : "+f"(d[0]), "+f"(d[1]), "+f"(d[2]), "+f"(d[3])
        : "r"(a[0]), "r"(a[1]), "r"(a[2]), "r"(a[3]), "r"(b[0]), "r"(b[1]));
}

__device__ __forceinline__ float h2f_round(float v) {
    return __half2float(__float2half_rn(v));
}

// ---- prepass: f32 (fp16-valued) -> packed fp16; 8 elems/thread, 16B stores ----
__global__ void cvt_k(const float4* __restrict__ a, const float4* __restrict__ b)
{
    size_t n8 = NELEM / 8;
    size_t stride = (size_t)gridDim.x * blockDim.x;
    for (size_t i = (size_t)blockIdx.x * blockDim.x + threadIdx.x; i < n8; i += stride) {
        float4 va0 = a[2 * i], va1 = a[2 * i + 1];
        __half2 h0 = __floats2half2_rn(va0.x, va0.y);
        __half2 h1 = __floats2half2_rn(va0.z, va0.w);
        __half2 h2 = __floats2half2_rn(va1.x, va1.y);
        __half2 h3 = __floats2half2_rn(va1.z, va1.w);
        uint4 ua = make_uint4(*reinterpret_cast<uint32_t*>(&h0),
                              *reinterpret_cast<uint32_t*>(&h1),
                              *reinterpret_cast<uint32_t*>(&h2),
                              *reinterpret_cast<uint32_t*>(&h3));
        *reinterpret_cast<uint4*>(&g_A[8 * i]) = ua;

        float4 vb0 = b[2 * i], vb1 = b[2 * i + 1];
        h0 = __floats2half2_rn(vb0.x, vb0.y);
        h1 = __floats2half2_rn(vb0.z, vb0.w);
        h2 = __floats2half2_rn(vb1.x, vb1.y);
        h3 = __floats2half2_rn(vb1.z, vb1.w);
        uint4 ub = make_uint4(*reinterpret_cast<uint32_t*>(&h0),
                              *reinterpret_cast<uint32_t*>(&h1),
                              *reinterpret_cast<uint32_t*>(&h2),
                              *reinterpret_cast<uint32_t*>(&h3));
        *reinterpret_cast<uint4*>(&g_B[8 * i]) = ub;
    }
}

// ---- main: 128x128 tile, 4 warps (2m x 2n) of 64x64, 3 CTAs/SM ----
__global__ void __launch_bounds__(TPB, 3)
triu_mm_k(float* __restrict__ C)
{
    int bid = blockIdx.x;
    int tid = threadIdx.x, wid = tid >> 5, lane = tid & 31;

    // 16-row supertile rasterization over the 64x64 tile grid (L2 reuse)
    int mt = ((bid >> 10) << 4) | (bid & 15);
    int nt = (bid & 1023) >> 4;
    int m0 = mt * 128, n0 = nt * 128;

    if (nt < mt) {                              // strictly-lower: zero-fill f32
        float* base = C + (size_t)m0 * GN + n0;
        uint4 z = make_uint4(0, 0, 0, 0);
        for (int i = tid; i < 128 * 32; i += TPB)
            *reinterpret_cast<uint4*>(base + (size_t)(i >> 5) * GN + ((i & 31) << 2)) = z;
        return;
    }

    extern __shared__ char smraw[];
    uint32_t sb = (smem_u32(smraw) + 1023u) & ~1023u;
    int warp_m = (wid & 1) * 64;                // 2m x 2n warps: 64x64 per warp
    int warp_n = (wid >> 1) * 64;

    float acc[4][8][4];
    #pragma unroll
    for (int i = 0; i < 4; i++)
        #pragma unroll
        for (int j = 0; j < 8; j++)
            #pragma unroll
            for (int k = 0; k < 4; k++) acc[i][j][k] = 0.0f;

    // hoisted LDSM offsets (relative to stage base); inner loop adds constants
    uint32_t a_off[4], b_off[4];
    #pragma unroll
    for (int mb = 0; mb < 4; mb++)
        a_off[mb] = (uint32_t)(warp_m + mb * 16 + (lane & 15)) * A_STRIDE
                    + ((lane >> 4) << 4);
    #pragma unroll
    for (int nb = 0; nb < 4; nb++)
        b_off[nb] = A_TILE + (uint32_t)(lane & 15) * B_STRIDE
                    + (uint32_t)(warp_n + nb * 16) * 2 + ((lane >> 4) << 4);

    auto load_stage = [&](int slot, int ks) {
        uint32_t abase = sb + slot * STAGE;
        uint32_t bbase = abase + A_TILE;
        int k0 = ks * KSTAGE;
        #pragma unroll
        for (int j = 0; j < 8; j++) {           // A: 128 rows x 8 x 16B
            int c = tid + j * TPB;
            int r = c >> 3, kc = c & 7;
            cpasync16(abase + r * A_STRIDE + kc * 16,
                      g_A + (size_t)(m0 + r) * GN + k0 + kc * 8);
        }
        #pragma unroll
        for (int j = 0; j < 8; j++) {           // B: 64 k-rows x 16 x 16B
            int c = tid + j * TPB;
            int kr = c >> 4, nc = c & 15;
            cpasync16(bbase + kr * B_STRIDE + nc * 16,
                      g_B + (size_t)(k0 + kr) * GN + n0 + nc * 8);
        }
        CP_COMMIT();
    };

    load_stage(0, 0);                           // prefetch stage 0

    for (int i = 0; i < NITERS; i++) {
        CP_WAIT0();                 // stage i fully resident
        __syncthreads();            // all warps past iter i-1 (slot (i+1)&1 free)
        if (i + 1 < NITERS)
            load_stage((i + 1) & 1, i + 1);     // overlaps compute below

        uint32_t abase = sb + (i & 1) * STAGE;
        #pragma unroll
        for (int kk = 0; kk < 4; kk++) {
            uint32_t af[4][4];
            uint32_t a_kk = abase + (kk << 5);          // +32B along K
            #pragma unroll
            for (int mb = 0; mb < 4; mb++)
                LDSM_X4(af[mb], a_kk + a_off[mb]);
            uint32_t b_kk = abase + kk * (16 * B_STRIDE);
            #pragma unroll
            for (int half = 0; half < 2; half++) {
                uint32_t bf[2][4];
                #pragma unroll
                for (int nb = 0; nb < 2; nb++)
                    LDSM_X4T(bf[nb], b_kk + b_off[half * 2 + nb]);
                #pragma unroll
                for (int mb = 0; mb < 4; mb++)
                    #pragma unroll
                    for (int nj = 0; nj < 4; nj++)
                        mma16816(acc[mb][half * 4 + nj], af[mb],
                                 &bf[nj >> 1][(nj & 1) * 2]);
            }
        }
    }

    // ---- epilogue: triu mask + fp16-rounded float32 stores ----
    #pragma unroll
    for (int mb = 0; mb < 4; mb++) {
        #pragma unroll
        for (int nj = 0; nj < 8; nj++) {
            int gr = m0 + warp_m + mb * 16 + (lane >> 2);
            int gc = n0 + warp_n + nj * 8 + ((lane & 3) << 1);
            float* d = acc[mb][nj];
            {
                float2 v;
                v.x = (gc >= gr)     ? h2f_round(d[0]) : 0.0f;
                v.y = (gc + 1 >= gr) ? h2f_round(d[1]) : 0.0f;
                *reinterpret_cast<float2*>(C + (size_t)gr * GN + gc) = v;
            }
            {
                int gr2 = gr + 8;
                float2 v;
                v.x = (gc >= gr2)     ? h2f_round(d[2]) : 0.0f;
                v.y = (gc + 1 >= gr2) ? h2f_round(d[3]) : 0.0f;
                *reinterpret_cast<float2*>(C + (size_t)gr2 * GN + gc) = v;
            }
        }
    }
}

extern "C" void kernel_launch(void* const* d_in, const int* in_sizes, int n_in,
                              void* d_out, int out_size)
{
    (void)in_sizes; (void)n_in; (void)out_size;
    cvt_k<<<16384, 256>>>((const float4*)d_in[0], (const float4*)d_in[1]);
    cudaFuncSetAttribute(triu_mm_k, cudaFuncAttributeMaxDynamicSharedMemorySize, SMEM_DYN);
    triu_mm_k<<<64 * 64, TPB, SMEM_DYN>>>((float*)d_out);
}